// round 1
// baseline (speedup 1.0000x reference)
#include <cuda_runtime.h>
#include <cstdint>

#define N_NODES 100000
#define N_EDGES 1600000
#define D 128
#define ND (N_NODES * D)
#define NEG_SLOPE 0.2f
#define INV_SQRT_D 0.08838834764831845f

// ---------------- scratch (device globals; no runtime allocation) ----------
__device__ float g_hq[ND];       // x @ W_q
__device__ float g_kact[ND];     // leaky(x @ W_k)
__device__ float g_hproj[ND];    // x @ W_l + b
__device__ float g_qagg[ND];     // segment_sum(h_q[col], row)
__device__ float g_acc[ND];      // output accumulator (pre-activation)
__device__ float g_scores[N_EDGES];
__device__ float g_expv[N_EDGES];
__device__ unsigned g_maxenc[N_NODES];
__device__ float g_sumexp[N_EDGES > N_NODES ? N_NODES : N_NODES];

// monotonic float<->uint encoding for atomicMax on floats
__device__ __forceinline__ unsigned encf(float f) {
    unsigned u = __float_as_uint(f);
    return (u & 0x80000000u) ? ~u : (u | 0x80000000u);
}
__device__ __forceinline__ float decf(unsigned u) {
    return __uint_as_float((u & 0x80000000u) ? (u & 0x7fffffffu) : ~u);
}
#define ENC_NEGINF 0x007FFFFFu   // encf(-inf)

// ---------------- init: zero accumulators, init segment max/sum ------------
__global__ void k_init() {
    size_t i = (size_t)blockIdx.x * blockDim.x + threadIdx.x;
    size_t stride = (size_t)gridDim.x * blockDim.x;
    float4 z = make_float4(0.f, 0.f, 0.f, 0.f);
    const size_t nd4 = ND / 4;
    for (size_t j = i; j < nd4; j += stride) {
        reinterpret_cast<float4*>(g_qagg)[j] = z;
        reinterpret_cast<float4*>(g_acc)[j]  = z;
    }
    for (size_t j = i; j < N_NODES; j += stride) {
        g_sumexp[j] = 0.f;
        g_maxenc[j] = ENC_NEGINF;
    }
}

// ---------------- fused GEMM: H = x @ {W_q | W_k | W_l} with epilogues -----
// BM=64, BN=64, BK=16, 256 threads, 4x4 per-thread tile.
#define BM 64
#define BN 64
#define BK 16
__global__ __launch_bounds__(256) void k_gemm(
    const float* __restrict__ x,
    const float* __restrict__ Wq,
    const float* __restrict__ Wk,
    const float* __restrict__ Wl,
    const float* __restrict__ bl)
{
    __shared__ float As[BK][BM + 1];   // [k][m], padded -> conflict-free
    __shared__ float Bs[BK][BN];       // [k][n]

    const int t = threadIdx.x;
    const int rowBlock = blockIdx.x * BM;
    const int cb = blockIdx.y;            // 0..5 -> 384 output cols
    const int w = cb >> 1;                // 0=Wq, 1=Wk, 2=Wl
    const int colInW = (cb & 1) * BN;     // 0 or 64
    const float* __restrict__ W = (w == 0) ? Wq : ((w == 1) ? Wk : Wl);

    const int ty = t >> 4;   // 0..15 -> m group
    const int tx = t & 15;   // 0..15 -> n group

    // load index decomposition
    const int la_m  = t >> 2;   // 0..63
    const int la_kq = t & 3;    // 0..3 (float4 chunk of 16 k's)
    const int lb_k  = t >> 4;   // 0..15
    const int lb_nq = t & 15;   // 0..15

    float acc[4][4];
#pragma unroll
    for (int i = 0; i < 4; i++)
#pragma unroll
        for (int j = 0; j < 4; j++) acc[i][j] = 0.f;

#pragma unroll
    for (int k0 = 0; k0 < D; k0 += BK) {
        // A tile: 64 rows x 16 k
        int gm = rowBlock + la_m;
        float4 av = make_float4(0.f, 0.f, 0.f, 0.f);
        if (gm < N_NODES)
            av = *reinterpret_cast<const float4*>(x + (size_t)gm * D + k0 + la_kq * 4);
        As[la_kq * 4 + 0][la_m] = av.x;
        As[la_kq * 4 + 1][la_m] = av.y;
        As[la_kq * 4 + 2][la_m] = av.z;
        As[la_kq * 4 + 3][la_m] = av.w;
        // B tile: 16 k x 64 n
        float4 bv = *reinterpret_cast<const float4*>(
            W + (size_t)(k0 + lb_k) * D + colInW + lb_nq * 4);
        *reinterpret_cast<float4*>(&Bs[lb_k][lb_nq * 4]) = bv;
        __syncthreads();

#pragma unroll
        for (int kk = 0; kk < BK; kk++) {
            float a0 = As[kk][ty * 4 + 0];
            float a1 = As[kk][ty * 4 + 1];
            float a2 = As[kk][ty * 4 + 2];
            float a3 = As[kk][ty * 4 + 3];
            float4 b = *reinterpret_cast<float4*>(&Bs[kk][tx * 4]);
            acc[0][0] += a0 * b.x; acc[0][1] += a0 * b.y; acc[0][2] += a0 * b.z; acc[0][3] += a0 * b.w;
            acc[1][0] += a1 * b.x; acc[1][1] += a1 * b.y; acc[1][2] += a1 * b.z; acc[1][3] += a1 * b.w;
            acc[2][0] += a2 * b.x; acc[2][1] += a2 * b.y; acc[2][2] += a2 * b.z; acc[2][3] += a2 * b.w;
            acc[3][0] += a3 * b.x; acc[3][1] += a3 * b.y; acc[3][2] += a3 * b.z; acc[3][3] += a3 * b.w;
        }
        __syncthreads();
    }

    // epilogue
#pragma unroll
    for (int i = 0; i < 4; i++) {
        int m = rowBlock + ty * 4 + i;
        if (m >= N_NODES) continue;
#pragma unroll
        for (int j = 0; j < 4; j++) {
            int n = colInW + tx * 4 + j;
            float v = acc[i][j];
            size_t off = (size_t)m * D + n;
            if (w == 0) {
                g_hq[off] = v;
            } else if (w == 1) {
                g_kact[off] = (v >= 0.f) ? v : NEG_SLOPE * v;
            } else {
                g_hproj[off] = v + bl[n];
            }
        }
    }
}

// ---------------- edge phase 1: q_agg[row] += h_q[col] ---------------------
// warp per edge, float4 per lane
__global__ __launch_bounds__(256) void k_scatter_qagg(const int* __restrict__ row,
                                                      const int* __restrict__ col)
{
    int e = blockIdx.x * 8 + (threadIdx.x >> 5);
    if (e >= N_EDGES) return;
    int lane = threadIdx.x & 31;
    int r = row[e], c = col[e];
    float4 v = *reinterpret_cast<const float4*>(g_hq + (size_t)c * D + lane * 4);
    float* dst = g_qagg + (size_t)r * D + lane * 4;
    atomicAdd(dst + 0, v.x);
    atomicAdd(dst + 1, v.y);
    atomicAdd(dst + 2, v.z);
    atomicAdd(dst + 3, v.w);
}

// ---------------- edge phase 2: scores + segment max -----------------------
__global__ __launch_bounds__(256) void k_scores(const int* __restrict__ row,
                                                const int* __restrict__ col)
{
    int e = blockIdx.x * 8 + (threadIdx.x >> 5);
    if (e >= N_EDGES) return;
    int lane = threadIdx.x & 31;
    int r = row[e], c = col[e];
    float4 a = *reinterpret_cast<const float4*>(g_kact + (size_t)r * D + lane * 4);
    float4 b = *reinterpret_cast<const float4*>(g_qagg + (size_t)c * D + lane * 4);
    float s = a.x * b.x + a.y * b.y + a.z * b.z + a.w * b.w;
#pragma unroll
    for (int o = 16; o; o >>= 1) s += __shfl_xor_sync(0xffffffffu, s, o);
    if (lane == 0) {
        s *= INV_SQRT_D;
        g_scores[e] = s;
        atomicMax(&g_maxenc[r], encf(s));
    }
}

// ---------------- edge phase 3: exp + segment sum --------------------------
__global__ __launch_bounds__(256) void k_softmax_sum(const int* __restrict__ row)
{
    int e = blockIdx.x * blockDim.x + threadIdx.x;
    if (e >= N_EDGES) return;
    int r = row[e];
    float m = decf(g_maxenc[r]);
    float ex = __expf(g_scores[e] - m);
    g_expv[e] = ex;
    atomicAdd(&g_sumexp[r], ex);
}

// ---------------- edge phase 4: acc[row] += alpha * h_proj[col] ------------
__global__ __launch_bounds__(256) void k_aggregate(const int* __restrict__ row,
                                                   const int* __restrict__ col)
{
    int e = blockIdx.x * 8 + (threadIdx.x >> 5);
    if (e >= N_EDGES) return;
    int lane = threadIdx.x & 31;
    int r = row[e], c = col[e];
    float alpha = g_expv[e] / (g_sumexp[r] + 1e-8f);
    float4 v = *reinterpret_cast<const float4*>(g_hproj + (size_t)c * D + lane * 4);
    float* dst = g_acc + (size_t)r * D + lane * 4;
    atomicAdd(dst + 0, alpha * v.x);
    atomicAdd(dst + 1, alpha * v.y);
    atomicAdd(dst + 2, alpha * v.z);
    atomicAdd(dst + 3, alpha * v.w);
}

// ---------------- final: leaky relu --------------------------------------
__global__ __launch_bounds__(256) void k_final(float* __restrict__ out)
{
    size_t i = (size_t)blockIdx.x * blockDim.x + threadIdx.x;
    const size_t nd4 = ND / 4;
    if (i >= nd4) return;
    float4 v = reinterpret_cast<const float4*>(g_acc)[i];
    v.x = (v.x >= 0.f) ? v.x : NEG_SLOPE * v.x;
    v.y = (v.y >= 0.f) ? v.y : NEG_SLOPE * v.y;
    v.z = (v.z >= 0.f) ? v.z : NEG_SLOPE * v.z;
    v.w = (v.w >= 0.f) ? v.w : NEG_SLOPE * v.w;
    reinterpret_cast<float4*>(out)[i] = v;
}

// ---------------- launch ---------------------------------------------------
extern "C" void kernel_launch(void* const* d_in, const int* in_sizes, int n_in,
                              void* d_out, int out_size)
{
    const float* x  = (const float*)d_in[0];
    const int* ei   = (const int*)d_in[1];
    const float* Wq = (const float*)d_in[2];
    const float* Wk = (const float*)d_in[3];
    // d_in[4] = W_v (dead in reference — skipped)
    const float* Wl = (const float*)d_in[5];
    const float* bl = (const float*)d_in[6];
    float* out = (float*)d_out;

    const int* row = ei;             // edge_index[0]
    const int* col = ei + N_EDGES;   // edge_index[1]

    k_init<<<2048, 256>>>();

    dim3 ggrid((N_NODES + BM - 1) / BM, 384 / BN);
    k_gemm<<<ggrid, 256>>>(x, Wq, Wk, Wl, bl);

    int edgeBlocks = (N_EDGES + 7) / 8;
    k_scatter_qagg<<<edgeBlocks, 256>>>(row, col);
    k_scores<<<edgeBlocks, 256>>>(row, col);
    k_softmax_sum<<<(N_EDGES + 255) / 256, 256>>>(row);
    k_aggregate<<<edgeBlocks, 256>>>(row, col);
    k_final<<<(ND / 4 + 255) / 256, 256>>>(out);
}

// round 3
// speedup vs baseline: 2.0864x; 2.0864x over previous
#include <cuda_runtime.h>
#include <cstdint>

#define N_NODES 100000
#define N_EDGES 1600000
#define D 128
#define ND (N_NODES * D)
#define NEG_SLOPE 0.2f
#define INV_SQRT_D 0.08838834764831845f

// ---------------- scratch (device globals; no runtime allocation) ----------
__device__ float g_hq[ND];       // x @ W_q
__device__ float g_kact[ND];     // leaky(x @ W_k)
__device__ float g_hproj[ND];    // x @ W_l + b
__device__ float g_qagg[ND];     // segment_sum(h_q[col], row)
__device__ float g_acc[ND];      // output accumulator (pre-activation)
__device__ float g_scores[N_EDGES];
__device__ float g_expv[N_EDGES];
__device__ unsigned g_maxenc[N_NODES];
__device__ float g_sumexp[N_NODES];

// monotonic float<->uint encoding for atomicMax on floats
__device__ __forceinline__ unsigned encf(float f) {
    unsigned u = __float_as_uint(f);
    return (u & 0x80000000u) ? ~u : (u | 0x80000000u);
}
__device__ __forceinline__ float decf(unsigned u) {
    return __uint_as_float((u & 0x80000000u) ? (u & 0x7fffffffu) : ~u);
}
#define ENC_NEGINF 0x007FFFFFu   // encf(-inf)

// no-return vectorized global float add (sm_90+)
__device__ __forceinline__ void red_add_v4(float* p, float4 v) {
    asm volatile("red.global.add.v4.f32 [%0], {%1, %2, %3, %4};"
                 :: "l"(p), "f"(v.x), "f"(v.y), "f"(v.z), "f"(v.w)
                 : "memory");
}

// ---------------- init: zero accumulators, init segment max/sum ------------
__global__ void k_init() {
    size_t i = (size_t)blockIdx.x * blockDim.x + threadIdx.x;
    size_t stride = (size_t)gridDim.x * blockDim.x;
    float4 z = make_float4(0.f, 0.f, 0.f, 0.f);
    const size_t nd4 = ND / 4;
    for (size_t j = i; j < nd4; j += stride) {
        reinterpret_cast<float4*>(g_qagg)[j] = z;
        reinterpret_cast<float4*>(g_acc)[j]  = z;
    }
    for (size_t j = i; j < N_NODES; j += stride) {
        g_sumexp[j] = 0.f;
        g_maxenc[j] = ENC_NEGINF;
    }
}

// ---------------- fused GEMM: H = x @ {W_q | W_k | W_l} with epilogues -----
// BM=128, BN=64, BK=16, 256 threads, 8x4 per-thread tile.
#define BM 128
#define BN 64
#define BK 16
__global__ __launch_bounds__(256) void k_gemm(
    const float* __restrict__ x,
    const float* __restrict__ Wq,
    const float* __restrict__ Wk,
    const float* __restrict__ Wl,
    const float* __restrict__ bl)
{
    __shared__ float As[BK][BM + 4];   // [k][m], padded
    __shared__ float Bs[BK][BN];       // [k][n]

    const int t = threadIdx.x;
    const int rowBlock = blockIdx.x * BM;
    const int cb = blockIdx.y;            // 0..5 -> 384 output cols
    const int w = cb >> 1;                // 0=Wq, 1=Wk, 2=Wl
    const int colInW = (cb & 1) * BN;     // 0 or 64
    const float* __restrict__ W = (w == 0) ? Wq : ((w == 1) ? Wk : Wl);

    const int ty = t >> 4;   // 0..15 -> m group of 8
    const int tx = t & 15;   // 0..15 -> n group of 4

    const int lb_k  = t >> 4;   // 0..15
    const int lb_nq = t & 15;   // 0..15

    float acc[8][4];
#pragma unroll
    for (int i = 0; i < 8; i++)
#pragma unroll
        for (int j = 0; j < 4; j++) acc[i][j] = 0.f;

#pragma unroll
    for (int k0 = 0; k0 < D; k0 += BK) {
        // A tile: 128 rows x 16 k  -> 512 float4 loads, 2 per thread
#pragma unroll
        for (int l = 0; l < 2; l++) {
            int idx = t + l * 256;
            int rA = idx >> 2;        // 0..127
            int kq = idx & 3;         // float4 chunk within 16 k
            int gm = rowBlock + rA;
            float4 av = make_float4(0.f, 0.f, 0.f, 0.f);
            if (gm < N_NODES)
                av = *reinterpret_cast<const float4*>(x + (size_t)gm * D + k0 + kq * 4);
            As[kq * 4 + 0][rA] = av.x;
            As[kq * 4 + 1][rA] = av.y;
            As[kq * 4 + 2][rA] = av.z;
            As[kq * 4 + 3][rA] = av.w;
        }
        // B tile: 16 k x 64 n -> 1 float4 per thread
        float4 bv = *reinterpret_cast<const float4*>(
            W + (size_t)(k0 + lb_k) * D + colInW + lb_nq * 4);
        *reinterpret_cast<float4*>(&Bs[lb_k][lb_nq * 4]) = bv;
        __syncthreads();

#pragma unroll
        for (int kk = 0; kk < BK; kk++) {
            float a[8];
#pragma unroll
            for (int i = 0; i < 8; i++) a[i] = As[kk][ty * 8 + i];
            float4 b = *reinterpret_cast<float4*>(&Bs[kk][tx * 4]);
#pragma unroll
            for (int i = 0; i < 8; i++) {
                acc[i][0] += a[i] * b.x;
                acc[i][1] += a[i] * b.y;
                acc[i][2] += a[i] * b.z;
                acc[i][3] += a[i] * b.w;
            }
        }
        __syncthreads();
    }

    // epilogue
#pragma unroll
    for (int i = 0; i < 8; i++) {
        int m = rowBlock + ty * 8 + i;
        if (m >= N_NODES) continue;
#pragma unroll
        for (int j = 0; j < 4; j++) {
            int n = colInW + tx * 4 + j;
            float v = acc[i][j];
            size_t off = (size_t)m * D + n;
            if (w == 0) {
                g_hq[off] = v;
            } else if (w == 1) {
                g_kact[off] = (v >= 0.f) ? v : NEG_SLOPE * v;
            } else {
                g_hproj[off] = v + bl[n];
            }
        }
    }
}

// ---------------- edge phase 1: q_agg[row] += h_q[col] ---------------------
// warp handles 4 edges; lane covers one float4 of the 128-float row.
#define EPW 4   // edges per warp
__global__ __launch_bounds__(256) void k_scatter_qagg(const int* __restrict__ row,
                                                      const int* __restrict__ col)
{
    int warpId = blockIdx.x * 8 + (threadIdx.x >> 5);
    int e0 = warpId * EPW;
    if (e0 >= N_EDGES) return;
    int lane = threadIdx.x & 31;

    int r[EPW], c[EPW];
    float4 v[EPW];
#pragma unroll
    for (int i = 0; i < EPW; i++) {
        int e = e0 + i;
        r[i] = (e < N_EDGES) ? __ldg(row + e) : 0;
        c[i] = (e < N_EDGES) ? __ldg(col + e) : 0;
    }
#pragma unroll
    for (int i = 0; i < EPW; i++)
        v[i] = *reinterpret_cast<const float4*>(g_hq + (size_t)c[i] * D + lane * 4);
#pragma unroll
    for (int i = 0; i < EPW; i++) {
        if (e0 + i < N_EDGES)
            red_add_v4(g_qagg + (size_t)r[i] * D + lane * 4, v[i]);
    }
}

// ---------------- edge phase 2: scores + segment max -----------------------
__global__ __launch_bounds__(256) void k_scores(const int* __restrict__ row,
                                                const int* __restrict__ col)
{
    int warpId = blockIdx.x * 8 + (threadIdx.x >> 5);
    int e0 = warpId * EPW;
    if (e0 >= N_EDGES) return;
    int lane = threadIdx.x & 31;

    int r[EPW], c[EPW];
#pragma unroll
    for (int i = 0; i < EPW; i++) {
        int e = e0 + i;
        r[i] = (e < N_EDGES) ? __ldg(row + e) : 0;
        c[i] = (e < N_EDGES) ? __ldg(col + e) : 0;
    }
    float4 a[EPW], b[EPW];
#pragma unroll
    for (int i = 0; i < EPW; i++) {
        a[i] = *reinterpret_cast<const float4*>(g_kact + (size_t)r[i] * D + lane * 4);
        b[i] = *reinterpret_cast<const float4*>(g_qagg + (size_t)c[i] * D + lane * 4);
    }
    float s[EPW];
#pragma unroll
    for (int i = 0; i < EPW; i++)
        s[i] = a[i].x * b[i].x + a[i].y * b[i].y + a[i].z * b[i].z + a[i].w * b[i].w;
#pragma unroll
    for (int o = 16; o; o >>= 1) {
#pragma unroll
        for (int i = 0; i < EPW; i++)
            s[i] += __shfl_xor_sync(0xffffffffu, s[i], o);
    }
    if (lane == 0) {
#pragma unroll
        for (int i = 0; i < EPW; i++) {
            int e = e0 + i;
            if (e < N_EDGES) {
                float sc = s[i] * INV_SQRT_D;
                g_scores[e] = sc;
                atomicMax(&g_maxenc[r[i]], encf(sc));
            }
        }
    }
}

// ---------------- edge phase 3: exp + segment sum --------------------------
__global__ __launch_bounds__(256) void k_softmax_sum(const int* __restrict__ row)
{
    int e = blockIdx.x * blockDim.x + threadIdx.x;
    if (e >= N_EDGES) return;
    int r = __ldg(row + e);
    float m = decf(g_maxenc[r]);
    float ex = __expf(g_scores[e] - m);
    g_expv[e] = ex;
    atomicAdd(&g_sumexp[r], ex);
}

// ---------------- edge phase 4: acc[row] += alpha * h_proj[col] ------------
__global__ __launch_bounds__(256) void k_aggregate(const int* __restrict__ row,
                                                   const int* __restrict__ col)
{
    int warpId = blockIdx.x * 8 + (threadIdx.x >> 5);
    int e0 = warpId * EPW;
    if (e0 >= N_EDGES) return;
    int lane = threadIdx.x & 31;

    int r[EPW], c[EPW];
    float al[EPW];
#pragma unroll
    for (int i = 0; i < EPW; i++) {
        int e = e0 + i;
        r[i] = (e < N_EDGES) ? __ldg(row + e) : 0;
        c[i] = (e < N_EDGES) ? __ldg(col + e) : 0;
    }
#pragma unroll
    for (int i = 0; i < EPW; i++) {
        int e = e0 + i;
        al[i] = (e < N_EDGES) ? (g_expv[e] / (g_sumexp[r[i]] + 1e-8f)) : 0.f;
    }
    float4 v[EPW];
#pragma unroll
    for (int i = 0; i < EPW; i++)
        v[i] = *reinterpret_cast<const float4*>(g_hproj + (size_t)c[i] * D + lane * 4);
#pragma unroll
    for (int i = 0; i < EPW; i++) {
        if (e0 + i < N_EDGES) {
            float4 w = make_float4(al[i] * v[i].x, al[i] * v[i].y,
                                   al[i] * v[i].z, al[i] * v[i].w);
            red_add_v4(g_acc + (size_t)r[i] * D + lane * 4, w);
        }
    }
}

// ---------------- final: leaky relu --------------------------------------
__global__ __launch_bounds__(256) void k_final(float* __restrict__ out)
{
    size_t i = (size_t)blockIdx.x * blockDim.x + threadIdx.x;
    const size_t nd4 = ND / 4;
    if (i >= nd4) return;
    float4 v = reinterpret_cast<const float4*>(g_acc)[i];
    v.x = (v.x >= 0.f) ? v.x : NEG_SLOPE * v.x;
    v.y = (v.y >= 0.f) ? v.y : NEG_SLOPE * v.y;
    v.z = (v.z >= 0.f) ? v.z : NEG_SLOPE * v.z;
    v.w = (v.w >= 0.f) ? v.w : NEG_SLOPE * v.w;
    reinterpret_cast<float4*>(out)[i] = v;
}

// ---------------- launch ---------------------------------------------------
extern "C" void kernel_launch(void* const* d_in, const int* in_sizes, int n_in,
                              void* d_out, int out_size)
{
    const float* x  = (const float*)d_in[0];
    const int* ei   = (const int*)d_in[1];
    const float* Wq = (const float*)d_in[2];
    const float* Wk = (const float*)d_in[3];
    // d_in[4] = W_v (dead in reference — skipped)
    const float* Wl = (const float*)d_in[5];
    const float* bl = (const float*)d_in[6];
    float* out = (float*)d_out;

    const int* row = ei;             // edge_index[0]
    const int* col = ei + N_EDGES;   // edge_index[1]

    k_init<<<2048, 256>>>();

    dim3 ggrid((N_NODES + BM - 1) / BM, 384 / BN);
    k_gemm<<<ggrid, 256>>>(x, Wq, Wk, Wl, bl);

    int warpBlocks = (N_EDGES / EPW + 7) / 8;   // 4 edges per warp, 8 warps/block
    k_scatter_qagg<<<warpBlocks, 256>>>(row, col);
    k_scores<<<warpBlocks, 256>>>(row, col);
    k_softmax_sum<<<(N_EDGES + 255) / 256, 256>>>(row);
    k_aggregate<<<warpBlocks, 256>>>(row, col);
    k_final<<<(ND / 4 + 255) / 256, 256>>>(out);
}

// round 4
// speedup vs baseline: 3.0188x; 1.4469x over previous
#include <cuda_runtime.h>
#include <cstdint>

#define N_NODES 100000
#define N_EDGES 1600000
#define D 128
#define ND (N_NODES * D)
#define NEG_SLOPE 0.2f
#define INV_SQRT_D 0.08838834764831845f
#define FULLMASK 0xffffffffu

// ---------------- scratch (device globals) ---------------------------------
__device__ float g_hq[ND];       // x @ W_q
__device__ float g_kact[ND];     // leaky(x @ W_k)
__device__ float g_hproj[ND];    // x @ W_l + b
__device__ float g_qagg[ND];     // segment_sum(h_q[col], row)
__device__ int   g_deg[N_NODES];
__device__ int   g_ptr[N_NODES + 1];
__device__ int   g_cursor[N_NODES];
__device__ int   g_blk[256];     // per-scan-block totals / offsets
__device__ int   g_csr_col[N_EDGES];

// ---------------- CSR build -------------------------------------------------
__global__ void k_zero_deg() {
    int i = blockIdx.x * blockDim.x + threadIdx.x;
    if (i < N_NODES) g_deg[i] = 0;
}

__global__ void k_hist(const int* __restrict__ row) {
    int e = blockIdx.x * blockDim.x + threadIdx.x;
    if (e < N_EDGES) atomicAdd(&g_deg[__ldg(row + e)], 1);
}

// scan1: blocks of 1024 elements, 256 threads x 4 elems. exclusive prefix
// within block written to g_ptr; block total to g_blk.
#define SCAN_ELEMS 1024
#define SCAN_NBLK ((N_NODES + SCAN_ELEMS - 1) / SCAN_ELEMS)
__global__ __launch_bounds__(256) void k_scan1() {
    __shared__ int warpsum[8];
    __shared__ int woff[8];
    int b = blockIdx.x, t = threadIdx.x;
    int base = b * SCAN_ELEMS + t * 4;
    int d0 = (base + 0 < N_NODES) ? g_deg[base + 0] : 0;
    int d1 = (base + 1 < N_NODES) ? g_deg[base + 1] : 0;
    int d2 = (base + 2 < N_NODES) ? g_deg[base + 2] : 0;
    int d3 = (base + 3 < N_NODES) ? g_deg[base + 3] : 0;
    int s = d0 + d1 + d2 + d3;

    int lane = t & 31, w = t >> 5;
    int v = s;
#pragma unroll
    for (int o = 1; o < 32; o <<= 1) {
        int u = __shfl_up_sync(FULLMASK, v, o);
        if (lane >= o) v += u;
    }
    if (lane == 31) warpsum[w] = v;
    __syncthreads();
    if (t == 0) {
        int a = 0;
#pragma unroll
        for (int i = 0; i < 8; i++) { int x = warpsum[i]; woff[i] = a; a += x; }
        g_blk[b] = a;
    }
    __syncthreads();
    int excl = v - s + woff[w];           // exclusive prefix of this thread's 4-group
    if (base + 0 < N_NODES) g_ptr[base + 0] = excl;
    if (base + 1 < N_NODES) g_ptr[base + 1] = excl + d0;
    if (base + 2 < N_NODES) g_ptr[base + 2] = excl + d0 + d1;
    if (base + 3 < N_NODES) g_ptr[base + 3] = excl + d0 + d1 + d2;
}

__global__ void k_scan2() {
    if (threadIdx.x == 0 && blockIdx.x == 0) {
        int a = 0;
        for (int b = 0; b < SCAN_NBLK; b++) { int t = g_blk[b]; g_blk[b] = a; a += t; }
        g_ptr[N_NODES] = N_EDGES;
    }
}

__global__ void k_scan3() {
    int i = blockIdx.x * blockDim.x + threadIdx.x;
    if (i < N_NODES) {
        int v = g_ptr[i] + g_blk[i / SCAN_ELEMS];
        g_ptr[i] = v;
        g_cursor[i] = v;
    }
}

__global__ void k_perm(const int* __restrict__ row, const int* __restrict__ col) {
    int e = blockIdx.x * blockDim.x + threadIdx.x;
    if (e >= N_EDGES) return;
    int r = __ldg(row + e);
    int pos = atomicAdd(&g_cursor[r], 1);
    g_csr_col[pos] = __ldg(col + e);
}

// ---------------- fused GEMM: H = x @ {W_q | W_k | W_l} with epilogues -----
#define BM 128
#define BN 64
#define BK 16
__global__ __launch_bounds__(256) void k_gemm(
    const float* __restrict__ x,
    const float* __restrict__ Wq,
    const float* __restrict__ Wk,
    const float* __restrict__ Wl,
    const float* __restrict__ bl)
{
    __shared__ float As[BK][BM + 4];
    __shared__ float Bs[BK][BN];

    const int t = threadIdx.x;
    const int rowBlock = blockIdx.x * BM;
    const int cb = blockIdx.y;            // 0..5
    const int w = cb >> 1;                // 0=Wq, 1=Wk, 2=Wl
    const int colInW = (cb & 1) * BN;
    const float* __restrict__ W = (w == 0) ? Wq : ((w == 1) ? Wk : Wl);

    const int ty = t >> 4;
    const int tx = t & 15;
    const int lb_k  = t >> 4;
    const int lb_nq = t & 15;

    float acc[8][4];
#pragma unroll
    for (int i = 0; i < 8; i++)
#pragma unroll
        for (int j = 0; j < 4; j++) acc[i][j] = 0.f;

#pragma unroll
    for (int k0 = 0; k0 < D; k0 += BK) {
#pragma unroll
        for (int l = 0; l < 2; l++) {
            int idx = t + l * 256;
            int rA = idx >> 2;
            int kq = idx & 3;
            int gm = rowBlock + rA;
            float4 av = make_float4(0.f, 0.f, 0.f, 0.f);
            if (gm < N_NODES)
                av = *reinterpret_cast<const float4*>(x + (size_t)gm * D + k0 + kq * 4);
            As[kq * 4 + 0][rA] = av.x;
            As[kq * 4 + 1][rA] = av.y;
            As[kq * 4 + 2][rA] = av.z;
            As[kq * 4 + 3][rA] = av.w;
        }
        float4 bv = *reinterpret_cast<const float4*>(
            W + (size_t)(k0 + lb_k) * D + colInW + lb_nq * 4);
        *reinterpret_cast<float4*>(&Bs[lb_k][lb_nq * 4]) = bv;
        __syncthreads();

#pragma unroll
        for (int kk = 0; kk < BK; kk++) {
            float a[8];
#pragma unroll
            for (int i = 0; i < 8; i++) a[i] = As[kk][ty * 8 + i];
            float4 b = *reinterpret_cast<float4*>(&Bs[kk][tx * 4]);
#pragma unroll
            for (int i = 0; i < 8; i++) {
                acc[i][0] += a[i] * b.x;
                acc[i][1] += a[i] * b.y;
                acc[i][2] += a[i] * b.z;
                acc[i][3] += a[i] * b.w;
            }
        }
        __syncthreads();
    }

#pragma unroll
    for (int i = 0; i < 8; i++) {
        int m = rowBlock + ty * 8 + i;
        if (m >= N_NODES) continue;
#pragma unroll
        for (int j = 0; j < 4; j++) {
            int n = colInW + tx * 4 + j;
            float v = acc[i][j];
            size_t off = (size_t)m * D + n;
            if (w == 0) {
                g_hq[off] = v;
            } else if (w == 1) {
                g_kact[off] = (v >= 0.f) ? v : NEG_SLOPE * v;
            } else {
                g_hproj[off] = v + bl[n];
            }
        }
    }
}

// ---------------- q_agg: per-node gather-sum of h_q[col] -------------------
__global__ __launch_bounds__(256) void k_qagg() {
    int n = blockIdx.x * 8 + (threadIdx.x >> 5);
    if (n >= N_NODES) return;
    int lane = threadIdx.x & 31;
    int beg = g_ptr[n], end = g_ptr[n + 1];

    float4 s = make_float4(0.f, 0.f, 0.f, 0.f);
    int p = beg;
    for (; p + 1 < end; p += 2) {
        int c0 = g_csr_col[p];
        int c1 = g_csr_col[p + 1];
        float4 a = *reinterpret_cast<const float4*>(g_hq + (size_t)c0 * D + lane * 4);
        float4 b = *reinterpret_cast<const float4*>(g_hq + (size_t)c1 * D + lane * 4);
        s.x += a.x + b.x; s.y += a.y + b.y; s.z += a.z + b.z; s.w += a.w + b.w;
    }
    if (p < end) {
        int c0 = g_csr_col[p];
        float4 a = *reinterpret_cast<const float4*>(g_hq + (size_t)c0 * D + lane * 4);
        s.x += a.x; s.y += a.y; s.z += a.z; s.w += a.w;
    }
    *reinterpret_cast<float4*>(g_qagg + (size_t)n * D + lane * 4) = s;
}

// ---------------- fused attention: online softmax + aggregate + leaky ------
__device__ __forceinline__ float warp_sum(float d) {
#pragma unroll
    for (int o = 16; o; o >>= 1) d += __shfl_xor_sync(FULLMASK, d, o);
    return d;
}

__global__ __launch_bounds__(256) void k_attn(float* __restrict__ out) {
    int n = blockIdx.x * 8 + (threadIdx.x >> 5);
    if (n >= N_NODES) return;
    int lane = threadIdx.x & 31;
    int beg = g_ptr[n], end = g_ptr[n + 1];

    float4 k4 = *reinterpret_cast<const float4*>(g_kact + (size_t)n * D + lane * 4);

    float m = __int_as_float(0xff800000);   // -inf
    float Z = 0.f;
    float4 acc = make_float4(0.f, 0.f, 0.f, 0.f);

    int p = beg;
    for (; p + 1 < end; p += 2) {
        int c0 = g_csr_col[p];
        int c1 = g_csr_col[p + 1];
        float4 q0 = *reinterpret_cast<const float4*>(g_qagg  + (size_t)c0 * D + lane * 4);
        float4 h0 = *reinterpret_cast<const float4*>(g_hproj + (size_t)c0 * D + lane * 4);
        float4 q1 = *reinterpret_cast<const float4*>(g_qagg  + (size_t)c1 * D + lane * 4);
        float4 h1 = *reinterpret_cast<const float4*>(g_hproj + (size_t)c1 * D + lane * 4);
        float d0 = k4.x * q0.x + k4.y * q0.y + k4.z * q0.z + k4.w * q0.w;
        float d1 = k4.x * q1.x + k4.y * q1.y + k4.z * q1.z + k4.w * q1.w;
#pragma unroll
        for (int o = 16; o; o >>= 1) {
            d0 += __shfl_xor_sync(FULLMASK, d0, o);
            d1 += __shfl_xor_sync(FULLMASK, d1, o);
        }
        float s0 = d0 * INV_SQRT_D;
        float s1 = d1 * INV_SQRT_D;
        // online update edge 0
        {
            float mn = fmaxf(m, s0);
            float sc = __expf(m - mn);
            float ev = __expf(s0 - mn);
            Z = Z * sc + ev;
            acc.x = acc.x * sc + ev * h0.x;
            acc.y = acc.y * sc + ev * h0.y;
            acc.z = acc.z * sc + ev * h0.z;
            acc.w = acc.w * sc + ev * h0.w;
            m = mn;
        }
        // online update edge 1
        {
            float mn = fmaxf(m, s1);
            float sc = __expf(m - mn);
            float ev = __expf(s1 - mn);
            Z = Z * sc + ev;
            acc.x = acc.x * sc + ev * h1.x;
            acc.y = acc.y * sc + ev * h1.y;
            acc.z = acc.z * sc + ev * h1.z;
            acc.w = acc.w * sc + ev * h1.w;
            m = mn;
        }
    }
    if (p < end) {
        int c0 = g_csr_col[p];
        float4 q0 = *reinterpret_cast<const float4*>(g_qagg  + (size_t)c0 * D + lane * 4);
        float4 h0 = *reinterpret_cast<const float4*>(g_hproj + (size_t)c0 * D + lane * 4);
        float d0 = k4.x * q0.x + k4.y * q0.y + k4.z * q0.z + k4.w * q0.w;
        d0 = warp_sum(d0);
        float s0 = d0 * INV_SQRT_D;
        float mn = fmaxf(m, s0);
        float sc = __expf(m - mn);
        float ev = __expf(s0 - mn);
        Z = Z * sc + ev;
        acc.x = acc.x * sc + ev * h0.x;
        acc.y = acc.y * sc + ev * h0.y;
        acc.z = acc.z * sc + ev * h0.z;
        acc.w = acc.w * sc + ev * h0.w;
        m = mn;
    }

    float inv = 1.f / (Z + 1e-8f);
    float4 o;
    o.x = acc.x * inv; o.y = acc.y * inv; o.z = acc.z * inv; o.w = acc.w * inv;
    o.x = (o.x >= 0.f) ? o.x : NEG_SLOPE * o.x;
    o.y = (o.y >= 0.f) ? o.y : NEG_SLOPE * o.y;
    o.z = (o.z >= 0.f) ? o.z : NEG_SLOPE * o.z;
    o.w = (o.w >= 0.f) ? o.w : NEG_SLOPE * o.w;
    *reinterpret_cast<float4*>(out + (size_t)n * D + lane * 4) = o;
}

// ---------------- launch ---------------------------------------------------
extern "C" void kernel_launch(void* const* d_in, const int* in_sizes, int n_in,
                              void* d_out, int out_size)
{
    const float* x  = (const float*)d_in[0];
    const int* ei   = (const int*)d_in[1];
    const float* Wq = (const float*)d_in[2];
    const float* Wk = (const float*)d_in[3];
    // d_in[4] = W_v (dead in reference — skipped)
    const float* Wl = (const float*)d_in[5];
    const float* bl = (const float*)d_in[6];
    float* out = (float*)d_out;

    const int* row = ei;             // edge_index[0]
    const int* col = ei + N_EDGES;   // edge_index[1]

    // CSR build
    k_zero_deg<<<(N_NODES + 255) / 256, 256>>>();
    k_hist<<<(N_EDGES + 255) / 256, 256>>>(row);
    k_scan1<<<SCAN_NBLK, 256>>>();
    k_scan2<<<1, 32>>>();
    k_scan3<<<(N_NODES + 255) / 256, 256>>>();
    k_perm<<<(N_EDGES + 255) / 256, 256>>>(row, col);

    // projections
    dim3 ggrid((N_NODES + BM - 1) / BM, 384 / BN);
    k_gemm<<<ggrid, 256>>>(x, Wq, Wk, Wl, bl);

    // edge pipeline (gather-only)
    int nodeBlocks = (N_NODES + 7) / 8;   // warp per node, 8 warps/block
    k_qagg<<<nodeBlocks, 256>>>();
    k_attn<<<nodeBlocks, 256>>>(out);
}